// round 9
// baseline (speedup 1.0000x reference)
#include <cuda_runtime.h>
#include <cuda_fp16.h>
#include <math.h>
#include <stdint.h>

#define BATCH 8
#define CDIM 512
#define HW 4096
#define CPG 16
#define EPSV 1e-6f

typedef __half h16;

// ---------------- device scratch ----------------
__device__ h16   g_qt[(size_t)BATCH * HW * CDIM];   // GN1 out [b][t][c]
__device__ h16   g_vt[(size_t)BATCH * HW * CDIM];   // GN2 out [b][t][c]
__device__ h16   g_w [(size_t)4 * CDIM * CDIM];     // wq,wk,wv,wo fp16
__device__ h16   g_qp[(size_t)BATCH * HW * CDIM];   // q proj [b][t][c]
__device__ h16   g_kp[(size_t)BATCH * HW * CDIM];   // k proj [b][t][c]
__device__ h16   g_vp[(size_t)BATCH * CDIM * HW];   // v proj [b][c][t]
__device__ h16   g_ot[(size_t)BATCH * HW * CDIM];   // attn out [b][t][c]
__device__ float g_sc[(size_t)BATCH * HW * HW];     // scores S[b][y][x] fp32
__device__ h16   g_p [(size_t)BATCH * HW * HW];     // softmax P[b][y][x] fp16

// ---------------- PTX helpers ----------------
__device__ __forceinline__ uint32_t smem_u32(const void* p) {
    uint32_t a;
    asm("{ .reg .u64 t; cvta.to.shared.u64 t, %1; cvt.u32.u64 %0, t; }" : "=r"(a) : "l"(p));
    return a;
}
__device__ __forceinline__ void cpa16(uint32_t d, const void* g) {
    asm volatile("cp.async.cg.shared.global [%0], [%1], 16;" :: "r"(d), "l"(g) : "memory");
}
__device__ __forceinline__ void ldm4(uint32_t* d, uint32_t addr) {
    asm volatile("ldmatrix.sync.aligned.m8n8.x4.shared.b16 {%0,%1,%2,%3}, [%4];"
                 : "=r"(d[0]), "=r"(d[1]), "=r"(d[2]), "=r"(d[3]) : "r"(addr));
}
#define MMA(d, a, b0, b1) \
    asm volatile("mma.sync.aligned.m16n8k16.row.col.f32.f16.f16.f32 " \
        "{%0,%1,%2,%3}, {%4,%5,%6,%7}, {%8,%9}, {%0,%1,%2,%3};" \
        : "+f"((d)[0]), "+f"((d)[1]), "+f"((d)[2]), "+f"((d)[3]) \
        : "r"((a)[0]), "r"((a)[1]), "r"((a)[2]), "r"((a)[3]), "r"(b0), "r"(b1))

// ---------------- fused double GroupNorm ----------------
__global__ __launch_bounds__(512)
void gn_fused(const float* __restrict__ x, h16* __restrict__ qt, h16* __restrict__ vt,
              const float* __restrict__ gamma, const float* __restrict__ beta) {
    const int grp = blockIdx.x, b = blockIdx.y;
    const int c0 = grp * CPG;
    const size_t base = ((size_t)b * CDIM + c0) * HW;
    const int tid = threadIdx.x, wid = tid >> 5, lane = tid & 31;

    const float4* xc = (const float4*)(x + base + (size_t)wid * HW);
    float s = 0.f, ss = 0.f;
    for (int i = lane; i < HW / 4; i += 32) {
        float4 v = xc[i];
        s  += v.x + v.y + v.z + v.w;
        ss += v.x * v.x + v.y * v.y + v.z * v.z + v.w * v.w;
    }
#pragma unroll
    for (int o = 16; o; o >>= 1) {
        s  += __shfl_xor_sync(~0u, s, o);
        ss += __shfl_xor_sync(~0u, ss, o);
    }
    __shared__ float Sc[CPG], Qc[CPG];
    __shared__ float A1[CPG], B1[CPG], A2[CPG], B2[CPG];
    if (lane == 0) { Sc[wid] = s; Qc[wid] = ss; }
    __syncthreads();
    if (tid == 0) {
        float St = 0.f, Qt = 0.f;
        for (int c = 0; c < CPG; c++) { St += Sc[c]; Qt += Qc[c]; }
        const float invN = 1.f / (float)(CPG * HW);
        float mu1 = St * invN;
        float r1 = rsqrtf(Qt * invN - mu1 * mu1 + EPSV);
        float s2 = 0.f, q2 = 0.f;
        for (int c = 0; c < CPG; c++) {
            float a1 = gamma[c0 + c] * r1;
            float b1 = beta[c0 + c] - mu1 * a1;
            A1[c] = a1; B1[c] = b1;
            s2 += a1 * Sc[c] + (float)HW * b1;
            q2 += a1 * a1 * Qc[c] + 2.f * a1 * b1 * Sc[c] + (float)HW * b1 * b1;
        }
        float mu2 = s2 * invN;
        float r2 = rsqrtf(q2 * invN - mu2 * mu2 + EPSV);
        for (int c = 0; c < CPG; c++) {
            float g = gamma[c0 + c];
            A2[c] = g * r2 * A1[c];
            B2[c] = g * r2 * (B1[c] - mu2) + beta[c0 + c];
        }
    }
    __syncthreads();

    h16* qh = qt + (size_t)b * HW * CDIM;
    h16* vh = vt + (size_t)b * HW * CDIM;
    for (int t = tid; t < HW; t += 512) {
        alignas(16) h16 h1[CPG], h2[CPG];
#pragma unroll
        for (int c = 0; c < CPG; c++) {
            float v = x[base + (size_t)c * HW + t];
            h1[c] = __float2half_rn(fmaf(v, A1[c], B1[c]));
            h2[c] = __float2half_rn(fmaf(v, A2[c], B2[c]));
        }
        size_t o = (size_t)t * CDIM + c0;
        *(uint4*)&qh[o] = *(uint4*)&h1[0]; *(uint4*)&qh[o + 8] = *(uint4*)&h1[8];
        *(uint4*)&vh[o] = *(uint4*)&h2[0]; *(uint4*)&vh[o + 8] = *(uint4*)&h2[8];
    }
}

// ---------------- weight fp32 -> fp16 ----------------
__global__ void wconv(const float* __restrict__ wq, const float* __restrict__ wk,
                      const float* __restrict__ wv, const float* __restrict__ wo,
                      h16* __restrict__ out) {
    int e = blockIdx.x * 256 + threadIdx.x;
    int w = e >> 18, i = e & 0x3FFFF;
    const float* src = (w == 0) ? wq : (w == 1) ? wk : (w == 2) ? wv : wo;
    out[(size_t)w * 262144 + i] = __float2half_rn(src[i]);
}

// ---------------- fp16 HMMA GEMM ----------------
// C[m][n] = alpha * sum_k A[m][k]*B[n][k] (+bias)(+res)*oscale
// 128(M) x 256(N) block, BK=32, 3-stage cp.async, 8 warps (64x64 warp tiles)
#define SA_BYTES 8192            // 128 rows * 64 B
#define SB_BYTES 16384           // 256 rows * 64 B
#define ST_BYTES (SA_BYTES + SB_BYTES)   // 24 KB
#define SMEM_TOT (3 * ST_BYTES)          // 72 KB

template <bool OUTF16, int BIAS /*0 none,1 bias[m],2 bias[n]*/, bool RES>
__global__ __launch_bounds__(256, 1)
void gemm16(const h16* __restrict__ A, size_t zA,
            const h16* __restrict__ B, size_t zB,
            void* __restrict__ C, size_t zC, int ldC, int K,
            const float* __restrict__ bias,
            const float* __restrict__ res, size_t zR,
            float alpha, float oscale) {
    extern __shared__ __align__(16) char smem[];
    const int tid = threadIdx.x, lane = tid & 31, wid = tid >> 5;
    const int warp_m = wid & 1, warp_n = wid >> 1;        // 2 x 4 warps
    const int bz = blockIdx.z;
    const int m0 = blockIdx.y * 128, n0 = blockIdx.x * 256;
    const uint32_t sbase = smem_u32(smem);

    const h16* Ab = A + zA * bz;
    const h16* Bb = B + zB * bz;

    const int nst = K >> 5;

    auto load_stage = [&](int stage, int k0) {
        const uint32_t sA = sbase + stage * ST_BYTES;
        const uint32_t sB = sA + SA_BYTES;
        // A: 128 rows x 4 chunks = 512 cp.async
#pragma unroll
        for (int i = 0; i < 2; i++) {
            const int c = tid + i * 256;
            const int row = c >> 2, u0 = c & 3;
            const uint32_t u = (uint32_t)u0 ^ ((row >> 1) & 3);
            cpa16(sA + row * 64 + u * 16, Ab + (size_t)(m0 + row) * K + k0 + u0 * 8);
        }
        // B: 256 rows x 4 chunks = 1024 cp.async
#pragma unroll
        for (int i = 0; i < 4; i++) {
            const int c = tid + i * 256;
            const int row = c >> 2, u0 = c & 3;
            const uint32_t u = (uint32_t)u0 ^ ((row >> 1) & 3);
            cpa16(sB + row * 64 + u * 16, Bb + (size_t)(n0 + row) * K + k0 + u0 * 8);
        }
    };

    float acc[4][8][4];
#pragma unroll
    for (int i = 0; i < 4; i++)
#pragma unroll
        for (int j = 0; j < 8; j++)
#pragma unroll
            for (int l = 0; l < 4; l++) acc[i][j][l] = 0.f;

    load_stage(0, 0);
    asm volatile("cp.async.commit_group;" ::: "memory");
    load_stage(1, 32);
    asm volatile("cp.async.commit_group;" ::: "memory");

    const int g = lane >> 3, r = lane & 7;

    for (int s = 0; s < nst; s++) {
        asm volatile("cp.async.wait_group %0;" :: "n"(1) : "memory");
        __syncthreads();
        if (s + 2 < nst) load_stage((s + 2) % 3, (s + 2) << 5);
        asm volatile("cp.async.commit_group;" ::: "memory");

        const uint32_t sA = sbase + (s % 3) * ST_BYTES;
        const uint32_t sB = sA + SA_BYTES;
#pragma unroll
        for (int kk = 0; kk < 2; kk++) {
            const int c0 = kk * 16 + (g >> 1) * 8;
            const int uu = c0 >> 3;
            uint32_t af[4][4], bf[4][4];
#pragma unroll
            for (int mt = 0; mt < 4; mt++) {
                const int row = warp_m * 64 + mt * 16 + r + (g & 1) * 8;
                const uint32_t u = (uint32_t)uu ^ ((row >> 1) & 3);
                ldm4(af[mt], sA + row * 64 + u * 16);
            }
#pragma unroll
            for (int nt = 0; nt < 4; nt++) {
                const int row = warp_n * 64 + nt * 16 + r + (g & 1) * 8;
                const uint32_t u = (uint32_t)uu ^ ((row >> 1) & 3);
                ldm4(bf[nt], sB + row * 64 + u * 16);
            }
#pragma unroll
            for (int mt = 0; mt < 4; mt++)
#pragma unroll
                for (int nn = 0; nn < 8; nn++) {
                    const int t4 = nn >> 1, hb = nn & 1;
                    MMA(acc[mt][nn], af[mt], bf[t4][hb], bf[t4][2 + hb]);
                }
        }
        __syncthreads();
    }
    asm volatile("cp.async.wait_group %0;" :: "n"(0) : "memory");

    // ---------------- epilogue ----------------
#pragma unroll
    for (int mt = 0; mt < 4; mt++) {
#pragma unroll
        for (int nn = 0; nn < 8; nn++) {
            const float* d = acc[mt][nn];
            const int mr = m0 + warp_m * 64 + mt * 16 + (lane >> 2);
            const int nc = n0 + warp_n * 64 + nn * 8 + (lane & 3) * 2;
#pragma unroll
            for (int hh = 0; hh < 2; hh++) {
                const int m = mr + hh * 8;
                float v0 = d[hh * 2 + 0] * alpha;
                float v1 = d[hh * 2 + 1] * alpha;
                if (BIAS == 1) { const float bm = bias[m]; v0 += bm; v1 += bm; }
                if (BIAS == 2) { v0 += bias[nc]; v1 += bias[nc + 1]; }
                if (RES) {
                    const float2 rr = *(const float2*)&res[zR * bz + (size_t)m * ldC + nc];
                    v0 = (v0 + rr.x) * oscale;
                    v1 = (v1 + rr.y) * oscale;
                }
                if (OUTF16) {
                    __half2 hv = __floats2half2_rn(v0, v1);
                    *(__half2*)((h16*)C + zC * bz + (size_t)m * ldC + nc) = hv;
                } else {
                    float2 f; f.x = v0; f.y = v1;
                    *(float2*)((float*)C + zC * bz + (size_t)m * ldC + nc) = f;
                }
            }
        }
    }
}

// ---------------- softmax over contiguous x of S[b][y][x] -> P fp16 ----------------
__global__ __launch_bounds__(256)
void softmax_k(const float* __restrict__ S, h16* __restrict__ P) {
    const int wid = threadIdx.x >> 5, lane = threadIdx.x & 31;
    const int row = blockIdx.x * 8 + wid, b = blockIdx.y;
    const float4* r4 = (const float4*)(S + ((size_t)b * HW + row) * HW);

    float m = -1e30f;
    for (int i = lane; i < HW / 4; i += 32) {
        float4 v = r4[i];
        m = fmaxf(m, fmaxf(fmaxf(v.x, v.y), fmaxf(v.z, v.w)));
    }
#pragma unroll
    for (int o = 16; o; o >>= 1) m = fmaxf(m, __shfl_xor_sync(~0u, m, o));
    float s = 0.f;
    for (int i = lane; i < HW / 4; i += 32) {
        float4 v = r4[i];
        s += __expf(v.x - m) + __expf(v.y - m) + __expf(v.z - m) + __expf(v.w - m);
    }
#pragma unroll
    for (int o = 16; o; o >>= 1) s += __shfl_xor_sync(~0u, s, o);
    const float inv = 1.f / s;

    h16* Ph = P + ((size_t)b * HW + row) * HW;
    for (int i = lane; i < HW / 4; i += 32) {
        float4 v = r4[i];
        alignas(8) h16 h[4];
        h[0] = __float2half_rn(__expf(v.x - m) * inv);
        h[1] = __float2half_rn(__expf(v.y - m) * inv);
        h[2] = __float2half_rn(__expf(v.z - m) * inv);
        h[3] = __float2half_rn(__expf(v.w - m) * inv);
        *(uint2*)&Ph[i * 4] = *(uint2*)&h[0];
    }
}

// ---------------- launch ----------------
extern "C" void kernel_launch(void* const* d_in, const int* in_sizes, int n_in,
                              void* d_out, int out_size) {
    const float* q     = (const float*)d_in[0];
    const float* gamma = (const float*)d_in[1];
    const float* beta  = (const float*)d_in[2];
    const float* wq    = (const float*)d_in[3];
    const float* bq    = (const float*)d_in[4];
    const float* wk    = (const float*)d_in[5];
    const float* bk    = (const float*)d_in[6];
    const float* wv    = (const float*)d_in[7];
    const float* bv    = (const float*)d_in[8];
    const float* wo    = (const float*)d_in[9];
    const float* bo    = (const float*)d_in[10];
    float* out = (float*)d_out;

    h16 *qt, *vt, *gw, *qp, *kp, *vp, *ot, *pp;
    float *sc;
    cudaGetSymbolAddress((void**)&qt, g_qt);
    cudaGetSymbolAddress((void**)&vt, g_vt);
    cudaGetSymbolAddress((void**)&gw, g_w);
    cudaGetSymbolAddress((void**)&qp, g_qp);
    cudaGetSymbolAddress((void**)&kp, g_kp);
    cudaGetSymbolAddress((void**)&vp, g_vp);
    cudaGetSymbolAddress((void**)&ot, g_ot);
    cudaGetSymbolAddress((void**)&pp, g_p);
    cudaGetSymbolAddress((void**)&sc, g_sc);

    cudaFuncSetAttribute(gemm16<true, 2, false>,  cudaFuncAttributeMaxDynamicSharedMemorySize, SMEM_TOT);
    cudaFuncSetAttribute(gemm16<true, 1, false>,  cudaFuncAttributeMaxDynamicSharedMemorySize, SMEM_TOT);
    cudaFuncSetAttribute(gemm16<false, 0, false>, cudaFuncAttributeMaxDynamicSharedMemorySize, SMEM_TOT);
    cudaFuncSetAttribute(gemm16<true, 0, false>,  cudaFuncAttributeMaxDynamicSharedMemorySize, SMEM_TOT);
    cudaFuncSetAttribute(gemm16<false, 1, true>,  cudaFuncAttributeMaxDynamicSharedMemorySize, SMEM_TOT);

    const size_t zT = (size_t)HW * CDIM;   // [t][c] batch stride
    const size_t zS = (size_t)HW * HW;
    const size_t W  = 262144;              // 512*512

    gn_fused<<<dim3(32, BATCH), 512>>>(q, qt, vt, gamma, beta);
    wconv<<<4096, 256>>>(wq, wk, wv, wo, gw);

    // q proj: C[t][c_out] = qt[t][k] * wq[c_out][k], bias over n
    gemm16<true, 2, false><<<dim3(2, 32, BATCH), 256, SMEM_TOT>>>(
        qt, zT, gw + 0 * W, 0, qp, zT, CDIM, CDIM, bq, nullptr, 0, 1.f, 1.f);
    // k proj: from vt
    gemm16<true, 2, false><<<dim3(2, 32, BATCH), 256, SMEM_TOT>>>(
        vt, zT, gw + 1 * W, 0, kp, zT, CDIM, CDIM, bk, nullptr, 0, 1.f, 1.f);
    // v proj: C[c_out][t] = wv[c_out][k] * vt[t][k], bias over m
    gemm16<true, 1, false><<<dim3(16, 4, BATCH), 256, SMEM_TOT>>>(
        gw + 2 * W, 0, vt, zT, vp, zT, HW, CDIM, bv, nullptr, 0, 1.f, 1.f);

    // scores S[y][x] = scale * qp[y]·kp[x]  (fp32 out)
    const float scale = 1.f / sqrtf((float)CDIM);
    gemm16<false, 0, false><<<dim3(16, 32, BATCH), 256, SMEM_TOT>>>(
        qp, zT, kp, zT, sc, zS, HW, CDIM, nullptr, nullptr, 0, scale, 1.f);

    // softmax over x -> P fp16
    softmax_k<<<dim3(HW / 8, BATCH), 256>>>(sc, pp);

    // attn out: C[y][c] = sum_x P[y][x] * vp[c][x]
    gemm16<true, 0, false><<<dim3(2, 32, BATCH), 256, SMEM_TOT>>>(
        pp, zS, vp, zT, ot, zT, CDIM, HW, nullptr, nullptr, 0, 1.f, 1.f);

    // out[c][t] = (wo[c][k]·ot[t][k] + bo[c] + q[c][t]) / sqrt(2)  (fp32 out)
    const float inv_sqrt2 = 0.70710678118654752440f;
    gemm16<false, 1, true><<<dim3(16, 4, BATCH), 256, SMEM_TOT>>>(
        gw + 3 * W, 0, ot, zT, out, (size_t)CDIM * HW, HW, CDIM,
        bo, q, (size_t)CDIM * HW, 1.f, inv_sqrt2);
}

// round 10
// speedup vs baseline: 1.2562x; 1.2562x over previous
#include <cuda_runtime.h>
#include <cuda_fp16.h>
#include <math.h>
#include <stdint.h>

#define BATCH 8
#define CDIM 512
#define HW 4096
#define CPG 16
#define EPSV 1e-6f

typedef __half h16;

// ---------------- device scratch ----------------
__device__ h16   g_qt[(size_t)BATCH * HW * CDIM];   // GN1 out [b][t][c]
__device__ h16   g_vt[(size_t)BATCH * HW * CDIM];   // GN2 out [b][t][c]
__device__ h16   g_w [(size_t)4 * CDIM * CDIM];     // wq,wk,wv,wo fp16
__device__ h16   g_qp[(size_t)BATCH * HW * CDIM];   // q proj [b][t][c]
__device__ h16   g_kp[(size_t)BATCH * HW * CDIM];   // k proj [b][t][c]
__device__ h16   g_vp[(size_t)BATCH * CDIM * HW];   // v proj [b][c][t]
__device__ h16   g_ot[(size_t)BATCH * HW * CDIM];   // attn out [b][t][c]
__device__ float g_sc[(size_t)BATCH * HW * HW];     // scores S[b][y][x] fp32
__device__ h16   g_p [(size_t)BATCH * HW * HW];     // softmax P[b][y][x] fp16

// ---------------- PTX helpers ----------------
__device__ __forceinline__ uint32_t smem_u32(const void* p) {
    uint32_t a;
    asm("{ .reg .u64 t; cvta.to.shared.u64 t, %1; cvt.u32.u64 %0, t; }" : "=r"(a) : "l"(p));
    return a;
}
__device__ __forceinline__ void cpa16(uint32_t d, const void* g) {
    asm volatile("cp.async.cg.shared.global [%0], [%1], 16;" :: "r"(d), "l"(g) : "memory");
}
__device__ __forceinline__ void ldm4(uint32_t* d, uint32_t addr) {
    asm volatile("ldmatrix.sync.aligned.m8n8.x4.shared.b16 {%0,%1,%2,%3}, [%4];"
                 : "=r"(d[0]), "=r"(d[1]), "=r"(d[2]), "=r"(d[3]) : "r"(addr));
}
#define MMA(d, a, b0, b1) \
    asm volatile("mma.sync.aligned.m16n8k16.row.col.f32.f16.f16.f32 " \
        "{%0,%1,%2,%3}, {%4,%5,%6,%7}, {%8,%9}, {%0,%1,%2,%3};" \
        : "+f"((d)[0]), "+f"((d)[1]), "+f"((d)[2]), "+f"((d)[3]) \
        : "r"((a)[0]), "r"((a)[1]), "r"((a)[2]), "r"((a)[3]), "r"(b0), "r"(b1))

// ---------------- fused double GroupNorm ----------------
__global__ __launch_bounds__(512)
void gn_fused(const float* __restrict__ x, h16* __restrict__ qt, h16* __restrict__ vt,
              const float* __restrict__ gamma, const float* __restrict__ beta) {
    const int grp = blockIdx.x, b = blockIdx.y;
    const int c0 = grp * CPG;
    const size_t base = ((size_t)b * CDIM + c0) * HW;
    const int tid = threadIdx.x, wid = tid >> 5, lane = tid & 31;

    const float4* xc = (const float4*)(x + base + (size_t)wid * HW);
    float s = 0.f, ss = 0.f;
    for (int i = lane; i < HW / 4; i += 32) {
        float4 v = xc[i];
        s  += v.x + v.y + v.z + v.w;
        ss += v.x * v.x + v.y * v.y + v.z * v.z + v.w * v.w;
    }
#pragma unroll
    for (int o = 16; o; o >>= 1) {
        s  += __shfl_xor_sync(~0u, s, o);
        ss += __shfl_xor_sync(~0u, ss, o);
    }
    __shared__ float Sc[CPG], Qc[CPG];
    __shared__ float A1[CPG], B1[CPG], A2[CPG], B2[CPG];
    if (lane == 0) { Sc[wid] = s; Qc[wid] = ss; }
    __syncthreads();
    if (tid == 0) {
        float St = 0.f, Qt = 0.f;
        for (int c = 0; c < CPG; c++) { St += Sc[c]; Qt += Qc[c]; }
        const float invN = 1.f / (float)(CPG * HW);
        float mu1 = St * invN;
        float r1 = rsqrtf(Qt * invN - mu1 * mu1 + EPSV);
        float s2 = 0.f, q2 = 0.f;
        for (int c = 0; c < CPG; c++) {
            float a1 = gamma[c0 + c] * r1;
            float b1 = beta[c0 + c] - mu1 * a1;
            A1[c] = a1; B1[c] = b1;
            s2 += a1 * Sc[c] + (float)HW * b1;
            q2 += a1 * a1 * Qc[c] + 2.f * a1 * b1 * Sc[c] + (float)HW * b1 * b1;
        }
        float mu2 = s2 * invN;
        float r2 = rsqrtf(q2 * invN - mu2 * mu2 + EPSV);
        for (int c = 0; c < CPG; c++) {
            float g = gamma[c0 + c];
            A2[c] = g * r2 * A1[c];
            B2[c] = g * r2 * (B1[c] - mu2) + beta[c0 + c];
        }
    }
    __syncthreads();

    h16* qh = qt + (size_t)b * HW * CDIM;
    h16* vh = vt + (size_t)b * HW * CDIM;
    for (int t = tid; t < HW; t += 512) {
        alignas(16) h16 h1[CPG], h2[CPG];
#pragma unroll
        for (int c = 0; c < CPG; c++) {
            float v = x[base + (size_t)c * HW + t];
            h1[c] = __float2half_rn(fmaf(v, A1[c], B1[c]));
            h2[c] = __float2half_rn(fmaf(v, A2[c], B2[c]));
        }
        size_t o = (size_t)t * CDIM + c0;
        *(uint4*)&qh[o] = *(uint4*)&h1[0]; *(uint4*)&qh[o + 8] = *(uint4*)&h1[8];
        *(uint4*)&vh[o] = *(uint4*)&h2[0]; *(uint4*)&vh[o + 8] = *(uint4*)&h2[8];
    }
}

// ---------------- weight fp32 -> fp16 ----------------
__global__ void wconv(const float* __restrict__ wq, const float* __restrict__ wk,
                      const float* __restrict__ wv, const float* __restrict__ wo,
                      h16* __restrict__ out) {
    int e = blockIdx.x * 256 + threadIdx.x;
    int w = e >> 18, i = e & 0x3FFFF;
    const float* src = (w == 0) ? wq : (w == 1) ? wk : (w == 2) ? wv : wo;
    out[(size_t)w * 262144 + i] = __float2half_rn(src[i]);
}

// ---------------- fp16 HMMA GEMM ----------------
// C[m][n] = alpha * sum_k A[m][k]*B[n][k] (+bias)(+res)*oscale
// 128x128 block, BK=64, 3-stage cp.async, 8 warps (32x64 warp tiles)
// smem rows are 128B; swizzle u = chunk ^ (row & 7) (Swizzle<3,4,3>)
#define SA_BYTES 16384           // 128 rows * 128 B
#define ST_BYTES 32768           // A + B
#define SMEM_TOT (3 * ST_BYTES)  // 96 KB

template <bool OUTF16, int BIAS /*0 none,1 bias[m],2 bias[n]*/, bool RES>
__global__ __launch_bounds__(256, 2)
void gemm16(const h16* __restrict__ A, size_t zA,
            const h16* __restrict__ B, size_t zB,
            void* __restrict__ C, size_t zC, int ldC, int K,
            const float* __restrict__ bias,
            const float* __restrict__ res, size_t zR,
            float alpha, float oscale) {
    extern __shared__ __align__(16) char smem[];
    const int tid = threadIdx.x, lane = tid & 31, wid = tid >> 5;
    const int warp_m = wid & 3, warp_n = wid >> 2;
    const int bz = blockIdx.z;
    const int m0 = blockIdx.y * 128, n0 = blockIdx.x * 128;
    const uint32_t sbase = smem_u32(smem);

    const h16* Ab = A + zA * bz;
    const h16* Bb = B + zB * bz;

    const int nst = K >> 6;

    auto load_stage = [&](int stage, int k0) {
        const uint32_t sA = sbase + stage * ST_BYTES;
        const uint32_t sB = sA + SA_BYTES;
        // A and B: 128 rows x 8 16B-chunks each = 1024 cp.async each
#pragma unroll
        for (int i = 0; i < 4; i++) {
            const int c = tid + i * 256;
            const int row = c >> 3, u0 = c & 7;
            const uint32_t u = (uint32_t)u0 ^ (row & 7);
            cpa16(sA + row * 128 + u * 16, Ab + (size_t)(m0 + row) * K + k0 + u0 * 8);
            cpa16(sB + row * 128 + u * 16, Bb + (size_t)(n0 + row) * K + k0 + u0 * 8);
        }
    };

    float acc[2][8][4];
#pragma unroll
    for (int i = 0; i < 2; i++)
#pragma unroll
        for (int j = 0; j < 8; j++)
#pragma unroll
            for (int l = 0; l < 4; l++) acc[i][j][l] = 0.f;

    load_stage(0, 0);
    asm volatile("cp.async.commit_group;" ::: "memory");
    load_stage(1, 64);
    asm volatile("cp.async.commit_group;" ::: "memory");

    const int g = lane >> 3, r = lane & 7;

    for (int s = 0; s < nst; s++) {
        asm volatile("cp.async.wait_group %0;" :: "n"(1) : "memory");
        __syncthreads();
        if (s + 2 < nst) load_stage((s + 2) % 3, (s + 2) << 6);
        asm volatile("cp.async.commit_group;" ::: "memory");

        const uint32_t sA = sbase + (s % 3) * ST_BYTES;
        const uint32_t sB = sA + SA_BYTES;
#pragma unroll
        for (int kk = 0; kk < 4; kk++) {
            const int c0 = kk * 16 + (g >> 1) * 8;   // halfword offset
            const int uu = c0 >> 3;                  // 16B chunk 0..7
            uint32_t af[2][4], bf[4][4];
#pragma unroll
            for (int mt = 0; mt < 2; mt++) {
                const int row = warp_m * 32 + mt * 16 + r + (g & 1) * 8;
                const uint32_t u = (uint32_t)uu ^ (row & 7);
                ldm4(af[mt], sA + row * 128 + u * 16);
            }
#pragma unroll
            for (int nt = 0; nt < 4; nt++) {
                const int row = warp_n * 64 + nt * 16 + r + (g & 1) * 8;
                const uint32_t u = (uint32_t)uu ^ (row & 7);
                ldm4(bf[nt], sB + row * 128 + u * 16);
            }
#pragma unroll
            for (int mt = 0; mt < 2; mt++)
#pragma unroll
                for (int nn = 0; nn < 8; nn++) {
                    const int t4 = nn >> 1, hb = nn & 1;
                    MMA(acc[mt][nn], af[mt], bf[t4][hb], bf[t4][2 + hb]);
                }
        }
        __syncthreads();
    }
    asm volatile("cp.async.wait_group %0;" :: "n"(0) : "memory");

    // ---------------- epilogue ----------------
#pragma unroll
    for (int mt = 0; mt < 2; mt++) {
#pragma unroll
        for (int nn = 0; nn < 8; nn++) {
            const float* d = acc[mt][nn];
            const int mr = m0 + warp_m * 32 + mt * 16 + (lane >> 2);
            const int nc = n0 + warp_n * 64 + nn * 8 + (lane & 3) * 2;
#pragma unroll
            for (int hh = 0; hh < 2; hh++) {
                const int m = mr + hh * 8;
                float v0 = d[hh * 2 + 0] * alpha;
                float v1 = d[hh * 2 + 1] * alpha;
                if (BIAS == 1) { const float bm = bias[m]; v0 += bm; v1 += bm; }
                if (BIAS == 2) { v0 += bias[nc]; v1 += bias[nc + 1]; }
                if (RES) {
                    const float2 rr = *(const float2*)&res[zR * bz + (size_t)m * ldC + nc];
                    v0 = (v0 + rr.x) * oscale;
                    v1 = (v1 + rr.y) * oscale;
                }
                if (OUTF16) {
                    __half2 hv = __floats2half2_rn(v0, v1);
                    *(__half2*)((h16*)C + zC * bz + (size_t)m * ldC + nc) = hv;
                } else {
                    float2 f; f.x = v0; f.y = v1;
                    *(float2*)((float*)C + zC * bz + (size_t)m * ldC + nc) = f;
                }
            }
        }
    }
}

// ---------------- softmax over contiguous x of S[b][y][x] -> P fp16 ----------------
__global__ __launch_bounds__(256)
void softmax_k(const float* __restrict__ S, h16* __restrict__ P) {
    const int wid = threadIdx.x >> 5, lane = threadIdx.x & 31;
    const int row = blockIdx.x * 8 + wid, b = blockIdx.y;
    const float4* r4 = (const float4*)(S + ((size_t)b * HW + row) * HW);

    float m = -1e30f;
    for (int i = lane; i < HW / 4; i += 32) {
        float4 v = r4[i];
        m = fmaxf(m, fmaxf(fmaxf(v.x, v.y), fmaxf(v.z, v.w)));
    }
#pragma unroll
    for (int o = 16; o; o >>= 1) m = fmaxf(m, __shfl_xor_sync(~0u, m, o));
    float s = 0.f;
    for (int i = lane; i < HW / 4; i += 32) {
        float4 v = r4[i];
        s += __expf(v.x - m) + __expf(v.y - m) + __expf(v.z - m) + __expf(v.w - m);
    }
#pragma unroll
    for (int o = 16; o; o >>= 1) s += __shfl_xor_sync(~0u, s, o);
    const float inv = 1.f / s;

    h16* Ph = P + ((size_t)b * HW + row) * HW;
    for (int i = lane; i < HW / 4; i += 32) {
        float4 v = r4[i];
        alignas(8) h16 h[4];
        h[0] = __float2half_rn(__expf(v.x - m) * inv);
        h[1] = __float2half_rn(__expf(v.y - m) * inv);
        h[2] = __float2half_rn(__expf(v.z - m) * inv);
        h[3] = __float2half_rn(__expf(v.w - m) * inv);
        *(uint2*)&Ph[i * 4] = *(uint2*)&h[0];
    }
}

// ---------------- launch ----------------
extern "C" void kernel_launch(void* const* d_in, const int* in_sizes, int n_in,
                              void* d_out, int out_size) {
    const float* q     = (const float*)d_in[0];
    const float* gamma = (const float*)d_in[1];
    const float* beta  = (const float*)d_in[2];
    const float* wq    = (const float*)d_in[3];
    const float* bq    = (const float*)d_in[4];
    const float* wk    = (const float*)d_in[5];
    const float* bk    = (const float*)d_in[6];
    const float* wv    = (const float*)d_in[7];
    const float* bv    = (const float*)d_in[8];
    const float* wo    = (const float*)d_in[9];
    const float* bo    = (const float*)d_in[10];
    float* out = (float*)d_out;

    h16 *qt, *vt, *gw, *qp, *kp, *vp, *ot, *pp;
    float *sc;
    cudaGetSymbolAddress((void**)&qt, g_qt);
    cudaGetSymbolAddress((void**)&vt, g_vt);
    cudaGetSymbolAddress((void**)&gw, g_w);
    cudaGetSymbolAddress((void**)&qp, g_qp);
    cudaGetSymbolAddress((void**)&kp, g_kp);
    cudaGetSymbolAddress((void**)&vp, g_vp);
    cudaGetSymbolAddress((void**)&ot, g_ot);
    cudaGetSymbolAddress((void**)&pp, g_p);
    cudaGetSymbolAddress((void**)&sc, g_sc);

    cudaFuncSetAttribute(gemm16<true, 2, false>,  cudaFuncAttributeMaxDynamicSharedMemorySize, SMEM_TOT);
    cudaFuncSetAttribute(gemm16<true, 1, false>,  cudaFuncAttributeMaxDynamicSharedMemorySize, SMEM_TOT);
    cudaFuncSetAttribute(gemm16<false, 0, false>, cudaFuncAttributeMaxDynamicSharedMemorySize, SMEM_TOT);
    cudaFuncSetAttribute(gemm16<true, 0, false>,  cudaFuncAttributeMaxDynamicSharedMemorySize, SMEM_TOT);
    cudaFuncSetAttribute(gemm16<false, 1, true>,  cudaFuncAttributeMaxDynamicSharedMemorySize, SMEM_TOT);

    const size_t zT = (size_t)HW * CDIM;   // [t][c] batch stride
    const size_t zS = (size_t)HW * HW;
    const size_t W  = 262144;              // 512*512

    gn_fused<<<dim3(32, BATCH), 512>>>(q, qt, vt, gamma, beta);
    wconv<<<4096, 256>>>(wq, wk, wv, wo, gw);

    // q proj: C[t][c_out] = qt[t][k] * wq[c_out][k], bias over n
    gemm16<true, 2, false><<<dim3(4, 32, BATCH), 256, SMEM_TOT>>>(
        qt, zT, gw + 0 * W, 0, qp, zT, CDIM, CDIM, bq, nullptr, 0, 1.f, 1.f);
    // k proj: from vt
    gemm16<true, 2, false><<<dim3(4, 32, BATCH), 256, SMEM_TOT>>>(
        vt, zT, gw + 1 * W, 0, kp, zT, CDIM, CDIM, bk, nullptr, 0, 1.f, 1.f);
    // v proj: C[c_out][t] = wv[c_out][k] * vt[t][k], bias over m
    gemm16<true, 1, false><<<dim3(32, 4, BATCH), 256, SMEM_TOT>>>(
        gw + 2 * W, 0, vt, zT, vp, zT, HW, CDIM, bv, nullptr, 0, 1.f, 1.f);

    // scores S[y][x] = scale * qp[y]·kp[x]  (fp32 out)
    const float scale = 1.f / sqrtf((float)CDIM);
    gemm16<false, 0, false><<<dim3(32, 32, BATCH), 256, SMEM_TOT>>>(
        qp, zT, kp, zT, sc, zS, HW, CDIM, nullptr, nullptr, 0, scale, 1.f);

    // softmax over x -> P fp16
    softmax_k<<<dim3(HW / 8, BATCH), 256>>>(sc, pp);

    // attn out: C[y][c] = sum_x P[y][x] * vp[c][x]
    gemm16<true, 0, false><<<dim3(4, 32, BATCH), 256, SMEM_TOT>>>(
        pp, zS, vp, zT, ot, zT, CDIM, HW, nullptr, nullptr, 0, 1.f, 1.f);

    // out[c][t] = (wo[c][k]·ot[t][k] + bo[c] + q[c][t]) / sqrt(2)  (fp32 out)
    const float inv_sqrt2 = 0.70710678118654752440f;
    gemm16<false, 1, true><<<dim3(32, 4, BATCH), 256, SMEM_TOT>>>(
        gw + 3 * W, 0, ot, zT, out, (size_t)CDIM * HW, HW, CDIM,
        bo, q, (size_t)CDIM * HW, 1.f, inv_sqrt2);
}

// round 11
// speedup vs baseline: 1.5404x; 1.2263x over previous
#include <cuda_runtime.h>
#include <cuda_fp16.h>
#include <math.h>
#include <stdint.h>

#define BATCH 8
#define CDIM 512
#define HW 4096
#define CPG 16
#define EPSV 1e-6f

typedef __half h16;

// ---------------- device scratch ----------------
__device__ h16   g_qt[(size_t)BATCH * HW * CDIM];   // GN1 out [b][t][c]
__device__ h16   g_vt[(size_t)BATCH * HW * CDIM];   // GN2 out [b][t][c]
__device__ h16   g_w [(size_t)4 * CDIM * CDIM];     // wq,wk,wv,wo fp16
__device__ h16   g_qp[(size_t)BATCH * HW * CDIM];   // q proj [b][t][c]
__device__ h16   g_kp[(size_t)BATCH * HW * CDIM];   // k proj [b][t][c]
__device__ h16   g_vp[(size_t)BATCH * CDIM * HW];   // v proj [b][c][t]
__device__ h16   g_ot[(size_t)BATCH * HW * CDIM];   // attn out [b][t][c]
__device__ h16   g_p [(size_t)BATCH * HW * HW];     // E = exp(scale*S) [b][y][x] fp16
__device__ float g_r [(size_t)BATCH * HW];          // row sums of E

// ---------------- PTX helpers ----------------
__device__ __forceinline__ uint32_t smem_u32(const void* p) {
    uint32_t a;
    asm("{ .reg .u64 t; cvta.to.shared.u64 t, %1; cvt.u32.u64 %0, t; }" : "=r"(a) : "l"(p));
    return a;
}
__device__ __forceinline__ void cpa16(uint32_t d, const void* g) {
    asm volatile("cp.async.cg.shared.global [%0], [%1], 16;" :: "r"(d), "l"(g) : "memory");
}
__device__ __forceinline__ void ldm4(uint32_t* d, uint32_t addr) {
    asm volatile("ldmatrix.sync.aligned.m8n8.x4.shared.b16 {%0,%1,%2,%3}, [%4];"
                 : "=r"(d[0]), "=r"(d[1]), "=r"(d[2]), "=r"(d[3]) : "r"(addr));
}
#define MMA(d, a, b0, b1) \
    asm volatile("mma.sync.aligned.m16n8k16.row.col.f32.f16.f16.f32 " \
        "{%0,%1,%2,%3}, {%4,%5,%6,%7}, {%8,%9}, {%0,%1,%2,%3};" \
        : "+f"((d)[0]), "+f"((d)[1]), "+f"((d)[2]), "+f"((d)[3]) \
        : "r"((a)[0]), "r"((a)[1]), "r"((a)[2]), "r"((a)[3]), "r"(b0), "r"(b1))

// ---------------- fused double GroupNorm ----------------
__global__ __launch_bounds__(512)
void gn_fused(const float* __restrict__ x, h16* __restrict__ qt, h16* __restrict__ vt,
              const float* __restrict__ gamma, const float* __restrict__ beta) {
    const int grp = blockIdx.x, b = blockIdx.y;
    const int c0 = grp * CPG;
    const size_t base = ((size_t)b * CDIM + c0) * HW;
    const int tid = threadIdx.x, wid = tid >> 5, lane = tid & 31;

    const float4* xc = (const float4*)(x + base + (size_t)wid * HW);
    float s = 0.f, ss = 0.f;
    for (int i = lane; i < HW / 4; i += 32) {
        float4 v = xc[i];
        s  += v.x + v.y + v.z + v.w;
        ss += v.x * v.x + v.y * v.y + v.z * v.z + v.w * v.w;
    }
#pragma unroll
    for (int o = 16; o; o >>= 1) {
        s  += __shfl_xor_sync(~0u, s, o);
        ss += __shfl_xor_sync(~0u, ss, o);
    }
    __shared__ float Sc[CPG], Qc[CPG];
    __shared__ float A1[CPG], B1[CPG], A2[CPG], B2[CPG];
    if (lane == 0) { Sc[wid] = s; Qc[wid] = ss; }
    __syncthreads();
    if (tid == 0) {
        float St = 0.f, Qt = 0.f;
        for (int c = 0; c < CPG; c++) { St += Sc[c]; Qt += Qc[c]; }
        const float invN = 1.f / (float)(CPG * HW);
        float mu1 = St * invN;
        float r1 = rsqrtf(Qt * invN - mu1 * mu1 + EPSV);
        float s2 = 0.f, q2 = 0.f;
        for (int c = 0; c < CPG; c++) {
            float a1 = gamma[c0 + c] * r1;
            float b1 = beta[c0 + c] - mu1 * a1;
            A1[c] = a1; B1[c] = b1;
            s2 += a1 * Sc[c] + (float)HW * b1;
            q2 += a1 * a1 * Qc[c] + 2.f * a1 * b1 * Sc[c] + (float)HW * b1 * b1;
        }
        float mu2 = s2 * invN;
        float r2 = rsqrtf(q2 * invN - mu2 * mu2 + EPSV);
        for (int c = 0; c < CPG; c++) {
            float g = gamma[c0 + c];
            A2[c] = g * r2 * A1[c];
            B2[c] = g * r2 * (B1[c] - mu2) + beta[c0 + c];
        }
    }
    __syncthreads();

    h16* qh = qt + (size_t)b * HW * CDIM;
    h16* vh = vt + (size_t)b * HW * CDIM;
    for (int t = tid; t < HW; t += 512) {
        alignas(16) h16 h1[CPG], h2[CPG];
#pragma unroll
        for (int c = 0; c < CPG; c++) {
            float v = x[base + (size_t)c * HW + t];
            h1[c] = __float2half_rn(fmaf(v, A1[c], B1[c]));
            h2[c] = __float2half_rn(fmaf(v, A2[c], B2[c]));
        }
        size_t o = (size_t)t * CDIM + c0;
        *(uint4*)&qh[o] = *(uint4*)&h1[0]; *(uint4*)&qh[o + 8] = *(uint4*)&h1[8];
        *(uint4*)&vh[o] = *(uint4*)&h2[0]; *(uint4*)&vh[o + 8] = *(uint4*)&h2[8];
    }
}

// ---------------- weight fp32 -> fp16, zero row sums ----------------
__global__ void wconv(const float* __restrict__ wq, const float* __restrict__ wk,
                      const float* __restrict__ wv, const float* __restrict__ wo,
                      h16* __restrict__ out, float* __restrict__ rz) {
    int e = blockIdx.x * 256 + threadIdx.x;
    int w = e >> 18, i = e & 0x3FFFF;
    const float* src = (w == 0) ? wq : (w == 1) ? wk : (w == 2) ? wv : wo;
    out[(size_t)w * 262144 + i] = __float2half_rn(src[i]);
    if (e < BATCH * HW) rz[e] = 0.f;
}

// ---------------- fp16 HMMA GEMM ----------------
// C[m][n] = f(alpha * sum_k A[m][k]*B[n][k])
// 128x128 block, BK=64, 3-stage cp.async, 8 warps (32x64 warp tiles)
// EXPOUT: C = exp(alpha*acc) fp16, rowsums atomicAdd'ed into rsum[bz*4096+m]
// NRM:    C *= 1/rsum[bz*4096+m]
#define SA_BYTES 16384           // 128 rows * 128 B
#define ST_BYTES 32768           // A + B
#define SMEM_TOT (3 * ST_BYTES)  // 96 KB

template <bool OUTF16, int BIAS /*0 none,1 bias[m],2 bias[n]*/, bool RES, bool EXPOUT, bool NRM>
__global__ __launch_bounds__(256, 2)
void gemm16(const h16* __restrict__ A, size_t zA,
            const h16* __restrict__ B, size_t zB,
            void* __restrict__ C, size_t zC, int ldC, int K,
            const float* __restrict__ bias,
            const float* __restrict__ res, size_t zR,
            float* __restrict__ rsum,
            float alpha, float oscale) {
    extern __shared__ __align__(16) char smem[];
    const int tid = threadIdx.x, lane = tid & 31, wid = tid >> 5;
    const int warp_m = wid & 3, warp_n = wid >> 2;
    const int bz = blockIdx.z;
    const int m0 = blockIdx.y * 128, n0 = blockIdx.x * 128;
    const uint32_t sbase = smem_u32(smem);

    const h16* Ab = A + zA * bz;
    const h16* Bb = B + zB * bz;

    const int nst = K >> 6;

    auto load_stage = [&](int stage, int k0) {
        const uint32_t sA = sbase + stage * ST_BYTES;
        const uint32_t sB = sA + SA_BYTES;
#pragma unroll
        for (int i = 0; i < 4; i++) {
            const int c = tid + i * 256;
            const int row = c >> 3, u0 = c & 7;
            const uint32_t u = (uint32_t)u0 ^ (row & 7);
            cpa16(sA + row * 128 + u * 16, Ab + (size_t)(m0 + row) * K + k0 + u0 * 8);
            cpa16(sB + row * 128 + u * 16, Bb + (size_t)(n0 + row) * K + k0 + u0 * 8);
        }
    };

    float acc[2][8][4];
#pragma unroll
    for (int i = 0; i < 2; i++)
#pragma unroll
        for (int j = 0; j < 8; j++)
#pragma unroll
            for (int l = 0; l < 4; l++) acc[i][j][l] = 0.f;

    load_stage(0, 0);
    asm volatile("cp.async.commit_group;" ::: "memory");
    load_stage(1, 64);
    asm volatile("cp.async.commit_group;" ::: "memory");

    const int g = lane >> 3, r = lane & 7;

    for (int s = 0; s < nst; s++) {
        asm volatile("cp.async.wait_group %0;" :: "n"(1) : "memory");
        __syncthreads();
        if (s + 2 < nst) load_stage((s + 2) % 3, (s + 2) << 6);
        asm volatile("cp.async.commit_group;" ::: "memory");

        const uint32_t sA = sbase + (s % 3) * ST_BYTES;
        const uint32_t sB = sA + SA_BYTES;
#pragma unroll
        for (int kk = 0; kk < 4; kk++) {
            const int c0 = kk * 16 + (g >> 1) * 8;
            const int uu = c0 >> 3;
            uint32_t af[2][4], bf[4][4];
#pragma unroll
            for (int mt = 0; mt < 2; mt++) {
                const int row = warp_m * 32 + mt * 16 + r + (g & 1) * 8;
                const uint32_t u = (uint32_t)uu ^ (row & 7);
                ldm4(af[mt], sA + row * 128 + u * 16);
            }
#pragma unroll
            for (int nt = 0; nt < 4; nt++) {
                const int row = warp_n * 64 + nt * 16 + r + (g & 1) * 8;
                const uint32_t u = (uint32_t)uu ^ (row & 7);
                ldm4(bf[nt], sB + row * 128 + u * 16);
            }
#pragma unroll
            for (int mt = 0; mt < 2; mt++)
#pragma unroll
                for (int nn = 0; nn < 8; nn++) {
                    const int t4 = nn >> 1, hb = nn & 1;
                    MMA(acc[mt][nn], af[mt], bf[t4][hb], bf[t4][2 + hb]);
                }
        }
        __syncthreads();
    }
    asm volatile("cp.async.wait_group %0;" :: "n"(0) : "memory");

    // ---------------- epilogue ----------------
#pragma unroll
    for (int mt = 0; mt < 2; mt++) {
#pragma unroll
        for (int hh = 0; hh < 2; hh++) {
            const int m = m0 + warp_m * 32 + mt * 16 + (lane >> 2) + hh * 8;
            float rowacc = 0.f;
            float ri = 1.f;
            if (NRM) ri = 1.0f / rsum[(size_t)bz * HW + m];
            const float bm = (BIAS == 1) ? bias[m] : 0.f;
#pragma unroll
            for (int nn = 0; nn < 8; nn++) {
                const int nc = n0 + warp_n * 64 + nn * 8 + (lane & 3) * 2;
                float v0 = acc[mt][nn][hh * 2 + 0] * alpha;
                float v1 = acc[mt][nn][hh * 2 + 1] * alpha;
                if (EXPOUT) { v0 = __expf(v0); v1 = __expf(v1); rowacc += v0 + v1; }
                if (BIAS == 1) { v0 += bm; v1 += bm; }
                if (BIAS == 2) { v0 += bias[nc]; v1 += bias[nc + 1]; }
                if (RES) {
                    const float2 rr = *(const float2*)&res[zR * bz + (size_t)m * ldC + nc];
                    v0 = (v0 + rr.x) * oscale;
                    v1 = (v1 + rr.y) * oscale;
                }
                if (NRM) { v0 *= ri; v1 *= ri; }
                if (OUTF16) {
                    __half2 hv = __floats2half2_rn(v0, v1);
                    *(__half2*)((h16*)C + zC * bz + (size_t)m * ldC + nc) = hv;
                } else {
                    float2 f; f.x = v0; f.y = v1;
                    *(float2*)((float*)C + zC * bz + (size_t)m * ldC + nc) = f;
                }
            }
            if (EXPOUT) {
                rowacc += __shfl_xor_sync(~0u, rowacc, 1);
                rowacc += __shfl_xor_sync(~0u, rowacc, 2);
                if ((lane & 3) == 0) atomicAdd(&rsum[(size_t)bz * HW + m], rowacc);
            }
        }
    }
}

// ---------------- launch ----------------
extern "C" void kernel_launch(void* const* d_in, const int* in_sizes, int n_in,
                              void* d_out, int out_size) {
    const float* q     = (const float*)d_in[0];
    const float* gamma = (const float*)d_in[1];
    const float* beta  = (const float*)d_in[2];
    const float* wq    = (const float*)d_in[3];
    const float* bq    = (const float*)d_in[4];
    const float* wk    = (const float*)d_in[5];
    const float* bk    = (const float*)d_in[6];
    const float* wv    = (const float*)d_in[7];
    const float* bv    = (const float*)d_in[8];
    const float* wo    = (const float*)d_in[9];
    const float* bo    = (const float*)d_in[10];
    float* out = (float*)d_out;

    h16 *qt, *vt, *gw, *qp, *kp, *vp, *ot, *pp;
    float *rs;
    cudaGetSymbolAddress((void**)&qt, g_qt);
    cudaGetSymbolAddress((void**)&vt, g_vt);
    cudaGetSymbolAddress((void**)&gw, g_w);
    cudaGetSymbolAddress((void**)&qp, g_qp);
    cudaGetSymbolAddress((void**)&kp, g_kp);
    cudaGetSymbolAddress((void**)&vp, g_vp);
    cudaGetSymbolAddress((void**)&ot, g_ot);
    cudaGetSymbolAddress((void**)&pp, g_p);
    cudaGetSymbolAddress((void**)&rs, g_r);

    cudaFuncSetAttribute(gemm16<true, 2, false, false, false>,  cudaFuncAttributeMaxDynamicSharedMemorySize, SMEM_TOT);
    cudaFuncSetAttribute(gemm16<true, 1, false, false, false>,  cudaFuncAttributeMaxDynamicSharedMemorySize, SMEM_TOT);
    cudaFuncSetAttribute(gemm16<true, 0, false, true, false>,   cudaFuncAttributeMaxDynamicSharedMemorySize, SMEM_TOT);
    cudaFuncSetAttribute(gemm16<true, 0, false, false, true>,   cudaFuncAttributeMaxDynamicSharedMemorySize, SMEM_TOT);
    cudaFuncSetAttribute(gemm16<false, 1, true, false, false>,  cudaFuncAttributeMaxDynamicSharedMemorySize, SMEM_TOT);

    const size_t zT = (size_t)HW * CDIM;   // [t][c] batch stride
    const size_t zS = (size_t)HW * HW;
    const size_t W  = 262144;              // 512*512

    gn_fused<<<dim3(32, BATCH), 512>>>(q, qt, vt, gamma, beta);
    wconv<<<4096, 256>>>(wq, wk, wv, wo, gw, rs);   // also zeroes rowsum buffer

    // q proj: C[t][c_out] = qt[t][k] * wq[c_out][k], bias over n
    gemm16<true, 2, false, false, false><<<dim3(4, 32, BATCH), 256, SMEM_TOT>>>(
        qt, zT, gw + 0 * W, 0, qp, zT, CDIM, CDIM, bq, nullptr, 0, nullptr, 1.f, 1.f);
    // k proj: from vt
    gemm16<true, 2, false, false, false><<<dim3(4, 32, BATCH), 256, SMEM_TOT>>>(
        vt, zT, gw + 1 * W, 0, kp, zT, CDIM, CDIM, bk, nullptr, 0, nullptr, 1.f, 1.f);
    // v proj: C[c_out][t] = wv[c_out][k] * vt[t][k], bias over m
    gemm16<true, 1, false, false, false><<<dim3(32, 4, BATCH), 256, SMEM_TOT>>>(
        gw + 2 * W, 0, vt, zT, vp, zT, HW, CDIM, bv, nullptr, 0, nullptr, 1.f, 1.f);

    // scores+exp: E[y][x] = exp(scale * qp[y]·kp[x]) fp16; rowsums -> rs
    const float scale = 1.f / sqrtf((float)CDIM);
    gemm16<true, 0, false, true, false><<<dim3(32, 32, BATCH), 256, SMEM_TOT>>>(
        qp, zT, kp, zT, pp, zS, HW, CDIM, nullptr, nullptr, 0, rs, scale, 1.f);

    // attn out: C[y][c] = (sum_x E[y][x] * vp[c][x]) / rs[y]
    gemm16<true, 0, false, false, true><<<dim3(4, 32, BATCH), 256, SMEM_TOT>>>(
        pp, zS, vp, zT, ot, zT, CDIM, HW, nullptr, nullptr, 0, rs, 1.f, 1.f);

    // out[c][t] = (wo[c][k]·ot[t][k] + bo[c] + q[c][t]) / sqrt(2)  (fp32 out)
    const float inv_sqrt2 = 0.70710678118654752440f;
    gemm16<false, 1, true, false, false><<<dim3(32, 4, BATCH), 256, SMEM_TOT>>>(
        gw + 3 * W, 0, ot, zT, out, (size_t)CDIM * HW, HW, CDIM,
        bo, q, (size_t)CDIM * HW, nullptr, 1.f, inv_sqrt2);
}